// round 2
// baseline (speedup 1.0000x reference)
#include <cuda_runtime.h>
#include <math.h>

#define BB 2048
#define FF 64
#define DD 512
#define AA 512
#define HH 8
#define HD 64

// Scratch (allocation-free rule: __device__ globals). Layout [b, h, f, d].
__device__ float g_Qc[(size_t)BB * HH * FF * HD];
__device__ float g_Kc[(size_t)BB * HH * FF * HD];
__device__ float g_V [(size_t)BB * HH * FF * HD];

// ---------------------------------------------------------------------------
// Kernel 1: projection GEMM + bias + (optional) mean-centering over field axis.
// One block computes a 64(F) x 128(N) tile of X[b] @ W for one projection.
// Since the tile spans ALL F rows, the column mean is block-local.
// grid = (4 ntiles, 2048 batches, 3 projections {Q,K,V}), block = 128 threads.
// Thread microtile: 8 rows x 8 cols (8x16 thread grid).
// ---------------------------------------------------------------------------
__global__ __launch_bounds__(128) void proj_kernel(
    const float* __restrict__ Xq, const float* __restrict__ Xk, const float* __restrict__ Xv,
    const float* __restrict__ Wq, const float* __restrict__ Wk, const float* __restrict__ Wv,
    const float* __restrict__ bq, const float* __restrict__ bk, const float* __restrict__ bv)
{
    const int nt = blockIdx.x;          // n-tile: cols [nt*128, nt*128+128)
    const int b  = blockIdx.y;          // batch
    const int p  = blockIdx.z;          // 0=Q, 1=K, 2=V

    const float* X    = (p == 0) ? Xq : (p == 1) ? Xk : Xv;
    const float* W    = (p == 0) ? Wq : (p == 1) ? Wk : Wv;
    const float* bias = (p == 0) ? bq : (p == 1) ? bk : bv;
    float*       dst  = (p == 0) ? g_Qc : (p == 1) ? g_Kc : g_V;
    const bool center = (p < 2);        // Q and K are mean-centered; V is not

    __shared__ float As[16][68];        // X tile, transposed [k][m], padded
    __shared__ float Bs[16][128];       // W tile [k][n]
    __shared__ float red[8][128];       // column partial sums for centering
    __shared__ float means[128];

    const int tid = threadIdx.x;
    const int tx  = tid & 15;           // 0..15 (col group: 8 cols each)
    const int ty  = tid >> 4;           // 0..7  (row group: 8 rows each)
    const int n0  = nt * 128;

    float acc[8][8];
    #pragma unroll
    for (int i = 0; i < 8; i++)
        #pragma unroll
        for (int j = 0; j < 8; j++) acc[i][j] = 0.f;

    const float* Xb = X + (size_t)b * FF * DD;

    for (int k0 = 0; k0 < DD; k0 += 16) {
        // Load X tile (64x16) into As transposed: As[k][m]
        #pragma unroll
        for (int i = 0; i < 2; i++) {
            int idx = tid + i * 128;                    // 0..255
            int row = idx >> 2;                         // 0..63
            int kv  = idx & 3;                          // 0..3 (float4 along k)
            float4 v = *reinterpret_cast<const float4*>(Xb + row * DD + k0 + kv * 4);
            As[kv * 4 + 0][row] = v.x;
            As[kv * 4 + 1][row] = v.y;
            As[kv * 4 + 2][row] = v.z;
            As[kv * 4 + 3][row] = v.w;
        }
        // Load W tile (16x128) into Bs
        #pragma unroll
        for (int i = 0; i < 4; i++) {
            int idx = tid + i * 128;                    // 0..511
            int kk  = idx >> 5;                         // 0..15
            int nv  = idx & 31;                         // 0..31 (float4 along n)
            *reinterpret_cast<float4*>(&Bs[kk][nv * 4]) =
                *reinterpret_cast<const float4*>(W + (size_t)(k0 + kk) * AA + n0 + nv * 4);
        }
        __syncthreads();

        #pragma unroll
        for (int kk = 0; kk < 16; kk++) {
            float4 a0 = *reinterpret_cast<const float4*>(&As[kk][ty * 8]);
            float4 a1 = *reinterpret_cast<const float4*>(&As[kk][ty * 8 + 4]);
            float4 b0 = *reinterpret_cast<const float4*>(&Bs[kk][tx * 8]);
            float4 b1 = *reinterpret_cast<const float4*>(&Bs[kk][tx * 8 + 4]);
            float a[8] = {a0.x, a0.y, a0.z, a0.w, a1.x, a1.y, a1.z, a1.w};
            float bv_[8] = {b0.x, b0.y, b0.z, b0.w, b1.x, b1.y, b1.z, b1.w};
            #pragma unroll
            for (int i = 0; i < 8; i++)
                #pragma unroll
                for (int j = 0; j < 8; j++)
                    acc[i][j] = fmaf(a[i], bv_[j], acc[i][j]);
        }
        __syncthreads();
    }

    // Bias
    #pragma unroll
    for (int j = 0; j < 8; j++) {
        float bj = bias[n0 + tx * 8 + j];
        #pragma unroll
        for (int i = 0; i < 8; i++) acc[i][j] += bj;
    }

    // Mean-centering over the 64 field rows (block-local)
    if (center) {
        #pragma unroll
        for (int j = 0; j < 8; j++) {
            float s = 0.f;
            #pragma unroll
            for (int i = 0; i < 8; i++) s += acc[i][j];
            red[ty][tx * 8 + j] = s;
        }
        __syncthreads();
        if (tid < 128) {
            float s = 0.f;
            #pragma unroll
            for (int r = 0; r < 8; r++) s += red[r][tid];
            means[tid] = s * (1.f / 64.f);
        }
        __syncthreads();
        #pragma unroll
        for (int j = 0; j < 8; j++) {
            float m = means[tx * 8 + j];
            #pragma unroll
            for (int i = 0; i < 8; i++) acc[i][j] -= m;
        }
    }

    // Store to [b,h,f,d] layout. Column group (8 wide, 8-aligned) never
    // crosses a 64-col head boundary.
    const int ng0 = n0 + tx * 8;
    const int h   = ng0 >> 6;
    const int d0  = ng0 & 63;
    float* dstb = dst + ((size_t)b * HH + h) * FF * HD;
    #pragma unroll
    for (int i = 0; i < 8; i++) {
        int f = ty * 8 + i;
        float4 v0 = make_float4(acc[i][0], acc[i][1], acc[i][2], acc[i][3]);
        float4 v1 = make_float4(acc[i][4], acc[i][5], acc[i][6], acc[i][7]);
        *reinterpret_cast<float4*>(dstb + f * HD + d0)     = v0;
        *reinterpret_cast<float4*>(dstb + f * HD + d0 + 4) = v1;
    }
}

// ---------------------------------------------------------------------------
// Kernel 2: per-(b,h) attention.
//   S = Qc @ Kc^T (64x64), P = softmax_rows(S) + 1  (unary term == 1),
//   O = P @ V, out = relu(O + query), head h writes cols [h*64, h*64+64).
// grid = B*H blocks, 256 threads, dynamic smem = 3 * 64*68 floats.
// ---------------------------------------------------------------------------
__global__ __launch_bounds__(256) void attn_kernel(
    const float* __restrict__ query, float* __restrict__ out)
{
    const int bh = blockIdx.x;
    const int b  = bh >> 3;
    const int h  = bh & 7;

    extern __shared__ float sm[];
    float* Qs = sm;                 // 64 x 68 (also reused as V tile later)
    float* Ks = sm + 64 * 68;
    float* Ss = sm + 2 * 64 * 68;

    const int tid = threadIdx.x;
    const int tx  = tid & 15;       // 0..15
    const int ty  = tid >> 4;       // 0..15
    const int q0  = ty * 4;
    const int k0  = tx * 4;

    const float* Qg = g_Qc + (size_t)bh * FF * HD;
    const float* Kg = g_Kc + (size_t)bh * FF * HD;
    const float* Vg = g_V  + (size_t)bh * FF * HD;

    // Load Qc, Kc tiles (4096 floats each = 1024 float4, 4 per thread)
    #pragma unroll
    for (int i = 0; i < 4; i++) {
        int idx = tid + i * 256;    // 0..1023
        int f   = idx >> 4;
        int dv  = idx & 15;
        *reinterpret_cast<float4*>(Qs + f * 68 + dv * 4) =
            *reinterpret_cast<const float4*>(Qg + f * 64 + dv * 4);
        *reinterpret_cast<float4*>(Ks + f * 68 + dv * 4) =
            *reinterpret_cast<const float4*>(Kg + f * 64 + dv * 4);
    }
    __syncthreads();

    // S = Qc @ Kc^T : 4x4 microtile per thread
    float s[4][4];
    #pragma unroll
    for (int i = 0; i < 4; i++)
        #pragma unroll
        for (int j = 0; j < 4; j++) s[i][j] = 0.f;

    for (int d = 0; d < 64; d += 4) {
        float4 a[4], c[4];
        #pragma unroll
        for (int i = 0; i < 4; i++) a[i] = *reinterpret_cast<const float4*>(Qs + (q0 + i) * 68 + d);
        #pragma unroll
        for (int j = 0; j < 4; j++) c[j] = *reinterpret_cast<const float4*>(Ks + (k0 + j) * 68 + d);
        #pragma unroll
        for (int i = 0; i < 4; i++) {
            #pragma unroll
            for (int j = 0; j < 4; j++) {
                s[i][j] = fmaf(a[i].x, c[j].x, s[i][j]);
                s[i][j] = fmaf(a[i].y, c[j].y, s[i][j]);
                s[i][j] = fmaf(a[i].z, c[j].z, s[i][j]);
                s[i][j] = fmaf(a[i].w, c[j].w, s[i][j]);
            }
        }
    }
    #pragma unroll
    for (int i = 0; i < 4; i++)
        #pragma unroll
        for (int j = 0; j < 4; j++)
            Ss[(q0 + i) * 68 + (k0 + j)] = s[i][j];
    __syncthreads();

    // Overwrite Qs with the V tile (Qc no longer needed)
    #pragma unroll
    for (int i = 0; i < 4; i++) {
        int idx = tid + i * 256;
        int f   = idx >> 4;
        int dv  = idx & 15;
        *reinterpret_cast<float4*>(Qs + f * 68 + dv * 4) =
            *reinterpret_cast<const float4*>(Vg + f * 64 + dv * 4);
    }

    // Row softmax over k, then add the degenerate unary term (+1).
    // 4 threads per row, 16 entries each.
    {
        int q    = tid >> 2;
        int part = tid & 3;
        float* row = Ss + q * 68 + part * 16;
        float mx = -INFINITY;
        #pragma unroll
        for (int j = 0; j < 16; j++) mx = fmaxf(mx, row[j]);
        mx = fmaxf(mx, __shfl_xor_sync(0xFFFFFFFFu, mx, 1));
        mx = fmaxf(mx, __shfl_xor_sync(0xFFFFFFFFu, mx, 2));
        float e[16];
        float sum = 0.f;
        #pragma unroll
        for (int j = 0; j < 16; j++) { e[j] = expf(row[j] - mx); sum += e[j]; }
        sum += __shfl_xor_sync(0xFFFFFFFFu, sum, 1);
        sum += __shfl_xor_sync(0xFFFFFFFFu, sum, 2);
        float inv = 1.f / sum;
        #pragma unroll
        for (int j = 0; j < 16; j++) row[j] = e[j] * inv + 1.0f;
    }
    __syncthreads();

    // O = P @ V : 4x4 microtile per thread, d-cols = tx*4..tx*4+3
    float o[4][4];
    #pragma unroll
    for (int i = 0; i < 4; i++)
        #pragma unroll
        for (int j = 0; j < 4; j++) o[i][j] = 0.f;

    float* Vs = Qs;
    for (int k = 0; k < 64; k += 4) {
        float4 p[4], v[4];
        #pragma unroll
        for (int i = 0; i < 4; i++) p[i] = *reinterpret_cast<const float4*>(Ss + (q0 + i) * 68 + k);
        #pragma unroll
        for (int kk = 0; kk < 4; kk++) v[kk] = *reinterpret_cast<const float4*>(Vs + (k + kk) * 68 + tx * 4);
        #pragma unroll
        for (int i = 0; i < 4; i++) {
            o[i][0] = fmaf(p[i].x, v[0].x, o[i][0]); o[i][1] = fmaf(p[i].x, v[0].y, o[i][1]);
            o[i][2] = fmaf(p[i].x, v[0].z, o[i][2]); o[i][3] = fmaf(p[i].x, v[0].w, o[i][3]);
            o[i][0] = fmaf(p[i].y, v[1].x, o[i][0]); o[i][1] = fmaf(p[i].y, v[1].y, o[i][1]);
            o[i][2] = fmaf(p[i].y, v[1].z, o[i][2]); o[i][3] = fmaf(p[i].y, v[1].w, o[i][3]);
            o[i][0] = fmaf(p[i].z, v[2].x, o[i][0]); o[i][1] = fmaf(p[i].z, v[2].y, o[i][1]);
            o[i][2] = fmaf(p[i].z, v[2].z, o[i][2]); o[i][3] = fmaf(p[i].z, v[2].w, o[i][3]);
            o[i][0] = fmaf(p[i].w, v[3].x, o[i][0]); o[i][1] = fmaf(p[i].w, v[3].y, o[i][1]);
            o[i][2] = fmaf(p[i].w, v[3].z, o[i][2]); o[i][3] = fmaf(p[i].w, v[3].w, o[i][3]);
        }
    }

    // Epilogue: residual + relu, write head slice
    const float* qry = query + (size_t)b * FF * (HH * HD) + h * HD;
    float*       ob  = out   + (size_t)b * FF * (HH * HD) + h * HD;
    #pragma unroll
    for (int i = 0; i < 4; i++) {
        int f = q0 + i;
        float4 qv = *reinterpret_cast<const float4*>(qry + (size_t)f * (HH * HD) + tx * 4);
        float4 r;
        r.x = fmaxf(o[i][0] + qv.x, 0.f);
        r.y = fmaxf(o[i][1] + qv.y, 0.f);
        r.z = fmaxf(o[i][2] + qv.z, 0.f);
        r.w = fmaxf(o[i][3] + qv.w, 0.f);
        *reinterpret_cast<float4*>(ob + (size_t)f * (HH * HD) + tx * 4) = r;
    }
}

// ---------------------------------------------------------------------------
extern "C" void kernel_launch(void* const* d_in, const int* in_sizes, int n_in,
                              void* d_out, int out_size)
{
    const float* query = (const float*)d_in[0];
    const float* key   = (const float*)d_in[1];
    const float* value = (const float*)d_in[2];
    const float* Wq    = (const float*)d_in[3];
    const float* bq    = (const float*)d_in[4];
    const float* Wk    = (const float*)d_in[5];
    const float* bk    = (const float*)d_in[6];
    const float* Wv    = (const float*)d_in[7];
    const float* bv    = (const float*)d_in[8];
    // d_in[9] (Wk2), d_in[10] (bk2) intentionally unused: the unary term is a
    // softmax over a size-1 axis == 1.0 everywhere, independent of K2.
    float* out = (float*)d_out;

    // Projections: Qc, Kc (centered) and V into scratch.
    dim3 g1(4, BB, 3);
    proj_kernel<<<g1, 128>>>(query, key, value, Wq, Wk, Wv, bq, bk, bv);

    // Attention + epilogue. 3 padded 64x68 fp32 tiles of dynamic smem.
    const int smem_bytes = 3 * 64 * 68 * (int)sizeof(float);  // 52224
    cudaFuncSetAttribute(attn_kernel, cudaFuncAttributeMaxDynamicSharedMemorySize, smem_bytes);
    attn_kernel<<<BB * HH, 256, smem_bytes>>>(query, out);
}